// round 8
// baseline (speedup 1.0000x reference)
#include <cuda_runtime.h>
#include <math.h>

// ---------------------------------------------------------------------------
// expression[c,g] = bias1[gene_ix[g]] + sum_{frags in bucket c*gene_n+g}
//                   dot(sin(coords[f,:,None]*freq+shift).reshape(40), w)
// Per-fragment scalar g0(x)+g1(y): two fixed 1-D LUTs + lerp (err ~3e-6).
// R8: sorted buckets + contiguous bucket-aligned block chunks -> each block
// exclusively owns a bucket range; run totals accumulated via store-once STS
// into a smem accumulator (no global atomics), coalesced bias+acc flush
// replaces the init kernel.
// ---------------------------------------------------------------------------

#define TAB      256
#define T_LO     (-9.0f)
#define T_HI     ( 9.0f)
#define FULL     0xffffffffu
#define CAP      4096
#define MAX_GENE 1024
#define NTHR     256
#define NWARP    (NTHR / 32)
#define NBLK     1184
#define NOSH     (-1000000)      // sentinel: no shared bucket

__device__ float2 g_tbl[2][TAB];     // (value, slope-to-next)

// ---------------------------------------------------------------------------
__global__ void table_kernel(const float* __restrict__ freqs,
                             const float* __restrict__ shifts,
                             const float* __restrict__ w)
{
    int gw   = blockIdx.x * (blockDim.x >> 5) + (threadIdx.x >> 5);
    int lane = threadIdx.x & 31;
    if (gw >= 2 * TAB) return;
    int which = gw / TAB;
    int k     = gw % TAB;
    const float step = (T_HI - T_LO) / (float)TAB;
    float x0 = T_LO + (float)k * step;
    float x1 = x0 + step;
    float v0 = 0.f, v1 = 0.f;
    if (lane < 20) {
        float f = freqs[lane], s = shifts[lane], c = w[which * 20 + lane];
        v0 = c * sinf(fmaf(x0, f, s));
        v1 = c * sinf(fmaf(x1, f, s));
    }
    #pragma unroll
    for (int off = 16; off; off >>= 1) {
        v0 += __shfl_down_sync(FULL, v0, off);
        v1 += __shfl_down_sync(FULL, v1, off);
    }
    if (lane == 0) g_tbl[which][k] = make_float2(v0, v1 - v0);
}

// ---------------------------------------------------------------------------
__device__ __forceinline__ float lerp1(const float2* __restrict__ s, float x)
{
    const float scale = (float)TAB / (T_HI - T_LO);
    const float offs  = -T_LO * scale;
    const float hi    = (float)TAB - 0.001f;
    float u = fminf(fmaxf(fmaf(x, scale, offs), 0.f), hi);
    int   k = (int)u;
    float fr = u - (float)k;
    float2 t = s[k];
    return fmaf(fr, t.y, t.x);
}

// First f >= s with ix[f] != ix[s-1]. Warp-cooperative. s in [1, F).
__device__ __forceinline__ int extf(const int* __restrict__ ix, int s, int F)
{
    int prev = __ldg(&ix[s - 1]);
    int lane = threadIdx.x & 31;
    for (int f = s; f < F; f += 32) {
        int v = (f + lane < F) ? __ldg(&ix[f + lane]) : (prev + 1);
        unsigned m = __ballot_sync(FULL, v != prev);
        if (m) return f + __ffs(m) - 1;
    }
    return F;
}

// Flush one complete run total into the block accumulator.
// Exclusive buckets: store-once STS. Boundary-shared buckets: smem atomic.
__device__ __forceinline__ void flushv(float* __restrict__ acc,
                                       int bucket, float val,
                                       int pLo, int pN, int shB1, int shB2)
{
    int idx = bucket - pLo;
    if (idx < 0 || idx >= pN) return;
    if (bucket == shB1 || bucket == shB2) atomicAdd(acc + idx, val);
    else acc[idx] = val;
}

// ---------------------------------------------------------------------------
__global__ void __launch_bounds__(NTHR)
main_kernel(const float4* __restrict__ coords2,   // 2 frags per float4
            const float2* __restrict__ coordsF,   // per-frag view
            const int*    __restrict__ ix,
            const float*  __restrict__ bias,
            const int*    __restrict__ gene_ix,
            float*        __restrict__ out,
            int F, int gene_n, int total)
{
    __shared__ float2 s0[TAB];
    __shared__ float2 s1[TAB];
    __shared__ float  bias_sm[MAX_GENE];
    __shared__ float  acc[CAP];
    __shared__ int    shext[2];

    int tid  = threadIdx.x;
    int lane = tid & 31;
    int wid  = tid >> 5;

    // Load LUT + permuted bias into smem.
    {
        const float2* src = &g_tbl[0][0];
        for (int i = tid; i < 2 * TAB; i += NTHR) {
            float2 v = src[i];
            if (i < TAB) s0[i] = v; else s1[i - TAB] = v;
        }
    }
    bool small_g = (gene_n <= MAX_GENE);
    if (small_g)
        for (int g = tid; g < gene_n; g += NTHR)
            bias_sm[g] = __ldg(&bias[__ldg(&gene_ix[g])]);

    // Chunk bounds (bucket-aligned via ext).
    int b  = blockIdx.x;
    int NB = gridDim.x;
    int sA = (int)((long long)b * F / NB);
    int sB = (int)((long long)(b + 1) * F / NB);
    if (wid == 0) {
        int e = (sA <= 0) ? 0 : ((sA >= F) ? F : extf(ix, sA, F));
        if (lane == 0) shext[0] = e;
    }
    if (wid == 1) {
        int e = (b == NB - 1) ? F : ((sB <= 0) ? 0 : ((sB >= F) ? F : extf(ix, sB, F)));
        if (lane == 0) shext[1] = e;
    }
    __syncthreads();
    int fsE = shext[0], feE = shext[1];

    int Lo = (b == 0)      ? 0     : (fsE < F ? __ldg(&ix[fsE]) : total);
    int Hi = (b == NB - 1) ? total : (feE < F ? __ldg(&ix[feE]) : total);

    // Quad-aligned interior + scalar edges.
    int qa = (fsE + 3) >> 2;
    int qb = feE >> 2;
    int headS = fsE, headE, tailS, tailE;
    if (qa >= qb) { qa = qb = 0; headE = feE; tailS = 0; tailE = 0; }
    else          { headE = 4 * qa; tailS = 4 * qb; tailE = feE; }

    // Per-warp quad sub-chunks + boundary-shared bucket ids.
    int nq  = qb - qa;
    int per = (nq + NWARP - 1) / NWARP;
    int ws  = qa + wid * per;
    int we  = min(ws + per, qb);
    int shB1 = NOSH, shB2 = NOSH;
    if (ws < we) {
        int pf = 4 * ws - 1;
        if (pf >= 0) shB1 = __ldg(&ix[pf]);
        int nf = 4 * we;
        if (nf < F)  shB2 = __ldg(&ix[nf]);
    }

    // Pass loop over the owned bucket range (normally one pass).
    for (int pLo = Lo; pLo < Hi; pLo += CAP) {
        int pN = min(Hi - pLo, CAP);

        for (int i = tid; i < pN; i += NTHR) acc[i] = 0.f;
        __syncthreads();

        // Scalar edge fragments (always atomic; rare).
        if (wid == 0) {
            for (int f = headS + lane; f < headE; f += 32) {
                float2 c = __ldg(&coordsF[f]);
                int bk = __ldg(&ix[f]);
                int idx = bk - pLo;
                if (idx >= 0 && idx < pN)
                    atomicAdd(acc + idx, lerp1(s0, c.x) + lerp1(s1, c.y));
            }
            for (int f = tailS + lane; f < tailE; f += 32) {
                float2 c = __ldg(&coordsF[f]);
                int bk = __ldg(&ix[f]);
                int idx = bk - pLo;
                if (idx >= 0 && idx < pN)
                    atomicAdd(acc + idx, lerp1(s0, c.x) + lerp1(s1, c.y));
            }
        }

        // Warp main loop with cross-window carry.
        int   carryB = NOSH;
        float carryV = 0.f;
        for (int base = ws; base < we; base += 32) {
            int  q     = base + lane;
            bool valid = q < we;

            float4 cA = make_float4(0,0,0,0), cB = make_float4(0,0,0,0);
            int4   bb = make_int4(NOSH - 1, NOSH - 1, NOSH - 1, NOSH - 1);
            if (valid) {
                cA = __ldcs(&coords2[2 * q]);
                cB = __ldcs(&coords2[2 * q + 1]);
                bb = __ldcs(&((const int4*)ix)[q]);
            }

            float v0 = lerp1(s0, cA.x) + lerp1(s1, cA.y);
            float v1 = lerp1(s0, cA.z) + lerp1(s1, cA.w);
            float v2 = lerp1(s0, cB.x) + lerp1(s1, cB.y);
            float v3 = lerp1(s0, cB.z) + lerp1(s1, cB.w);

            // Carry: merge into lane0's first fragment, or flush (complete run).
            if (lane == 0) {
                if (bb.x == carryB) v0 += carryV;
                else flushv(acc, carryB, carryV, pLo, pN, shB1, shB2);
            }

            bool e01 = (bb.x == bb.y), e12 = (bb.y == bb.z), e23 = (bb.z == bb.w);
            float c0 = v0;
            float c1 = v1 + (e01 ? c0 : 0.f);
            float c2 = v2 + (e12 ? c1 : 0.f);
            float c3 = v3 + (e23 ? c2 : 0.f);
            bool  same = e01 && e12 && e23;
            float hsum = !e01 ? c0 : (!e12 ? c1 : c2);

            int  st_prev = __shfl_up_sync(FULL, bb.w, 1);
            bool cont    = (lane > 0) && same && (st_prev == bb.w);

            unsigned hb    = __ballot_sync(FULL, !cont);
            unsigned below = hb & (0xffffffffu >> (31 - lane));
            int seg = 31 - __clz(below);               // bit 0 always set

            float S = c3;
            #pragma unroll
            for (int off = 1; off < 32; off <<= 1) {
                float n = __shfl_up_sync(FULL, S, off);
                if (lane - off >= seg) S += n;
            }

            float Sprev = __shfl_up_sync(FULL, S, 1);
            int   nb0   = __shfl_down_sync(FULL, bb.x, 1);
            bool consumed = (lane < 31) && (nb0 == bb.w);

            bool f_int1 = valid && !e12 && !e01;
            bool f_int2 = valid && !e23 && !(e01 && e12);
            bool f_head = valid && !same;
            bool f_tail = valid && !consumed && (lane != 31);  // lane31 -> carry
            float hv = hsum + ((lane > 0 && st_prev == bb.x) ? Sprev : 0.f);

            if (f_int1) flushv(acc, bb.y, c1, pLo, pN, shB1, shB2);
            if (f_int2) flushv(acc, bb.z, c2, pLo, pN, shB1, shB2);
            if (f_head) flushv(acc, bb.x, hv, pLo, pN, shB1, shB2);
            if (f_tail) flushv(acc, bb.w, S,  pLo, pN, shB1, shB2);

            carryB = __shfl_sync(FULL, bb.w, 31);
            carryV = __shfl_sync(FULL, S,    31);
        }
        if (ws < we && lane == 0)
            flushv(acc, carryB, carryV, pLo, pN, shB1, shB2);

        __syncthreads();

        // Coalesced flush: bias + accumulated sums (also covers gap buckets).
        if (small_g) {
            for (int i = tid; i < pN; i += NTHR) {
                int bkt = pLo + i;
                out[bkt] = bias_sm[bkt % gene_n] + acc[i];
            }
        } else {
            for (int i = tid; i < pN; i += NTHR) {
                int bkt = pLo + i;
                out[bkt] = __ldg(&bias[__ldg(&gene_ix[bkt % gene_n])]) + acc[i];
            }
        }
        __syncthreads();
    }
}

// ---------------------------------------------------------------------------
extern "C" void kernel_launch(void* const* d_in, const int* in_sizes, int n_in,
                              void* d_out, int out_size)
{
    // 0 coords, 1 cellxgene_ix, 2 cell_n, 3 gene_n, 4 gene_ix,
    // 5 frequencies, 6 shifts, 7 weight1, 8 bias1
    int off = (n_in >= 9) ? 0 : -2;

    const float* coords  = (const float*)d_in[0];
    const int*   ix      = (const int*)  d_in[1];
    const int*   gene_ix = (const int*)  d_in[4 + off];
    const float* freqs   = (const float*)d_in[5 + off];
    const float* shifts  = (const float*)d_in[6 + off];
    const float* w       = (const float*)d_in[7 + off];
    const float* bias    = (const float*)d_in[8 + off];

    int F      = in_sizes[0] / 2;
    int gene_n = in_sizes[4 + off];
    float* out = (float*)d_out;

    table_kernel<<<(2 * TAB * 32 + NTHR - 1) / NTHR, NTHR>>>(freqs, shifts, w);

    main_kernel<<<NBLK, NTHR>>>((const float4*)coords, (const float2*)coords,
                                ix, bias, gene_ix, out, F, gene_n, out_size);
}

// round 9
// speedup vs baseline: 1.2947x; 1.2947x over previous
#include <cuda_runtime.h>
#include <math.h>

// ---------------------------------------------------------------------------
// expression[c,g] = bias1[gene_ix[g]] + sum_{frags in bucket c*gene_n+g}
//                   dot(sin(coords[f,:,None]*freq+shift).reshape(40), w)
// Per-fragment scalar g0(x)+g1(y): two fixed 1-D LUTs + lerp (err ~3e-6).
// R9: ONE fused launch. Phase A builds the LUT + inits out=bias (all blocks);
// software grid barrier (all 1036 blocks co-resident by construction);
// Phase B = proven R5 frag loop: 4 frags/lane branchless run combine, one
// segmented scan per 128 fragments, predicated global RED per distinct bucket.
// ---------------------------------------------------------------------------

#define TAB      256
#define T_LO     (-9.0f)
#define T_HI     ( 9.0f)
#define FULL     0xffffffffu
#define NTHR     256
#define NBLK     1036            // 7 blocks/SM x 148 SMs -> all co-resident
#define MAX_GENE 1024

__device__ float2 g_tbl[2][TAB];             // (value, slope-to-next)
__device__ unsigned long long g_arrive;      // zero-init; monotonic epochs

// ---------------------------------------------------------------------------
__device__ __forceinline__ float lerp1(const float2* __restrict__ s, float x)
{
    const float scale = (float)TAB / (T_HI - T_LO);
    const float offs  = -T_LO * scale;
    const float hi    = (float)TAB - 0.001f;
    float u = fminf(fmaxf(fmaf(x, scale, offs), 0.f), hi);
    int   k = (int)u;
    float fr = u - (float)k;
    float2 t = s[k];
    return fmaf(fr, t.y, t.x);
}

// All-blocks-resident grid barrier (monotonic epoch counter, self-advancing).
__device__ __forceinline__ void grid_barrier()
{
    __shared__ unsigned long long tgt;
    __syncthreads();
    if (threadIdx.x == 0) {
        __threadfence();                               // release phase-A writes
        unsigned long long my = atomicAdd(&g_arrive, 1ULL);
        tgt = (my / NBLK + 1ULL) * NBLK;
    }
    __syncthreads();
    if (threadIdx.x == 0) {
        unsigned long long cur;
        for (;;) {
            asm volatile("ld.global.acquire.gpu.u64 %0, [%1];"
                         : "=l"(cur) : "l"(&g_arrive) : "memory");
            if (cur >= tgt) break;
            __nanosleep(64);
        }
    }
    __syncthreads();
}

// ---------------------------------------------------------------------------
__global__ void __launch_bounds__(NTHR, 7)
fused_kernel(const float4* __restrict__ coords2,   // 2 frags per float4
             const float2* __restrict__ coordsF,
             const int*    __restrict__ ix,
             const int4*   __restrict__ ix4,
             const float*  __restrict__ freqs,
             const float*  __restrict__ shifts,
             const float*  __restrict__ w,
             const float*  __restrict__ bias,
             const int*    __restrict__ gene_ix,
             float*        __restrict__ out,
             int nquads, int F, int gene_n, int total)
{
    __shared__ float2 s0[TAB];
    __shared__ float2 s1[TAB];
    __shared__ float  bias_sm[MAX_GENE];

    int tid  = threadIdx.x;
    int lane = tid & 31;
    int wid  = tid >> 5;
    int b    = blockIdx.x;

    // ---------------- Phase A: LUT build + out init ----------------
    // Blocks 0..63: one warp per table point (512 points total).
    if (b < 64) {
        int gw = b * (NTHR / 32) + wid;           // 0..511
        int which = gw / TAB;
        int k     = gw % TAB;
        const float step = (T_HI - T_LO) / (float)TAB;
        float x0 = T_LO + (float)k * step;
        float x1 = x0 + step;
        float v0 = 0.f, v1 = 0.f;
        if (lane < 20) {
            float f = freqs[lane], s = shifts[lane], c = w[which * 20 + lane];
            v0 = c * sinf(fmaf(x0, f, s));
            v1 = c * sinf(fmaf(x1, f, s));
        }
        #pragma unroll
        for (int off = 16; off; off >>= 1) {
            v0 += __shfl_down_sync(FULL, v0, off);
            v1 += __shfl_down_sync(FULL, v1, off);
        }
        if (lane == 0) g_tbl[which][k] = make_float2(v0, v1 - v0);
    }

    // Every block inits its slice of out = bias[gene_ix[col]].
    bool small_g = (gene_n <= MAX_GENE) && (total % gene_n == 0);
    if (small_g) {
        for (int g = tid; g < gene_n; g += NTHR)
            bias_sm[g] = __ldg(&bias[__ldg(&gene_ix[g])]);
        __syncthreads();
        int rows = total / gene_n;
        int rpb  = (rows + NBLK - 1) / NBLK;
        int r0   = b * rpb;
        int r1   = min(r0 + rpb, rows);
        for (int r = r0; r < r1; ++r) {
            long base = (long)r * gene_n;
            for (int g = tid; g < gene_n; g += NTHR)
                out[base + g] = bias_sm[g];
        }
    } else {
        int chunk = (total + NBLK - 1) / NBLK;
        long i0 = (long)b * chunk;
        long i1 = min((long)total, i0 + chunk);
        for (long i = i0 + tid; i < i1; i += NTHR)
            out[i] = __ldg(&bias[__ldg(&gene_ix[(int)(i % gene_n)])]);
    }

    // ---------------- Barrier: table + init visible everywhere -------------
    grid_barrier();

    // ---------------- Phase B: R5 frag loop ----------------
    {
        const float2* src = &g_tbl[0][0];
        for (int i = tid; i < 2 * TAB; i += NTHR) {
            float2 v = src[i];
            if (i < TAB) s0[i] = v; else s1[i - TAB] = v;
        }
    }
    __syncthreads();

    // Leftover fragments (F % 4): one thread.
    if (b == 0 && tid == 0) {
        for (int f = 4 * nquads; f < F; ++f) {
            float2 c = __ldg(&coordsF[f]);
            atomicAdd(out + __ldg(&ix[f]), lerp1(s0, c.x) + lerp1(s1, c.y));
        }
    }

    int gwarp  = (b * NTHR + tid) >> 5;
    int nwarps = (NBLK * NTHR) >> 5;

    for (long qbase = (long)gwarp * 32; qbase < (long)nquads;
         qbase += (long)nwarps * 32) {
        long q     = qbase + lane;
        bool valid = q < (long)nquads;

        float4 cA = make_float4(0,0,0,0), cB = make_float4(0,0,0,0);
        int4   bb = make_int4(-1,-1,-1,-1);
        if (valid) {
            cA = __ldcs(&coords2[2 * q]);
            cB = __ldcs(&coords2[2 * q + 1]);
            bb = __ldcs(&ix4[q]);
        }

        float v0 = lerp1(s0, cA.x) + lerp1(s1, cA.y);
        float v1 = lerp1(s0, cA.z) + lerp1(s1, cA.w);
        float v2 = lerp1(s0, cB.x) + lerp1(s1, cB.y);
        float v3 = lerp1(s0, cB.z) + lerp1(s1, cB.w);

        // Branchless cumulative run sums over the 4 sorted buckets.
        bool e01 = (bb.x == bb.y), e12 = (bb.y == bb.z), e23 = (bb.z == bb.w);
        float c0 = v0;
        float c1 = v1 + (e01 ? c0 : 0.f);
        float c2 = v2 + (e12 ? c1 : 0.f);
        float c3 = v3 + (e23 ? c2 : 0.f);
        bool  same = e01 && e12 && e23;
        float hsum = !e01 ? c0 : (!e12 ? c1 : c2);

        // Tail run (bucket bb.w, sum c3) feeds the cross-lane segmented scan.
        int  st_prev = __shfl_up_sync(FULL, bb.w, 1);
        bool cont    = (lane > 0) && same && (st_prev == bb.w);

        unsigned hb    = __ballot_sync(FULL, !cont);
        unsigned below = hb & (0xffffffffu >> (31 - lane));
        int seg = 31 - __clz(below);                 // bit 0 always set

        float S = c3;
        #pragma unroll
        for (int off = 1; off < 32; off <<= 1) {
            float n = __shfl_up_sync(FULL, S, off);
            if (lane - off >= seg) S += n;
        }

        float Sprev = __shfl_up_sync(FULL, S, 1);
        int   nb0   = __shfl_down_sync(FULL, bb.x, 1);
        bool consumed = (lane < 31) && (nb0 == bb.w);

        bool f_int1 = valid && !e12 && !e01;
        bool f_int2 = valid && !e23 && !(e01 && e12);
        bool f_head = valid && !same;
        bool f_tail = valid && !consumed;
        float hv = hsum + ((lane > 0 && st_prev == bb.x) ? Sprev : 0.f);

        if (f_int1) atomicAdd(out + bb.y, c1);
        if (f_int2) atomicAdd(out + bb.z, c2);
        if (f_head) atomicAdd(out + bb.x, hv);
        if (f_tail) atomicAdd(out + bb.w, S);
    }
}

// ---------------------------------------------------------------------------
extern "C" void kernel_launch(void* const* d_in, const int* in_sizes, int n_in,
                              void* d_out, int out_size)
{
    // 0 coords, 1 cellxgene_ix, 2 cell_n, 3 gene_n, 4 gene_ix,
    // 5 frequencies, 6 shifts, 7 weight1, 8 bias1
    int off = (n_in >= 9) ? 0 : -2;

    const float* coords  = (const float*)d_in[0];
    const int*   ix      = (const int*)  d_in[1];
    const int*   gene_ix = (const int*)  d_in[4 + off];
    const float* freqs   = (const float*)d_in[5 + off];
    const float* shifts  = (const float*)d_in[6 + off];
    const float* w       = (const float*)d_in[7 + off];
    const float* bias    = (const float*)d_in[8 + off];

    int F      = in_sizes[0] / 2;
    int gene_n = in_sizes[4 + off];
    float* out = (float*)d_out;
    int nquads = F / 4;

    fused_kernel<<<NBLK, NTHR>>>((const float4*)coords, (const float2*)coords,
                                 ix, (const int4*)ix,
                                 freqs, shifts, w, bias, gene_ix,
                                 out, nquads, F, gene_n, out_size);
}